// round 1
// baseline (speedup 1.0000x reference)
#include <cuda_runtime.h>
#include <cuda_bf16.h>
#include <float.h>

// Problem constants
#define BB   8
#define NN   2048
#define MM   512
#define CC   256      // channels per source (C1 = C2 = 256)
#define NR   4
#define CIN  512      // C1 + C2
#define CO   256      // output channels of both MLP layers
#define PTOT (BB*NR*NN)   // 65536 positions

// ---------------- scratch (device globals; no runtime allocation) ----------------
__device__ float g_Kt[BB*NR*MM*CC];        // known_feats transposed (b,r,m,c)  16 MB
__device__ float g_interp[BB*CC*NR*NN];    // interpolated feats (b,c,r,n)      64 MB
__device__ float g_y1[(size_t)BB*CO*NR*NN];// GEMM1 raw output                  64 MB
__device__ float g_y2[(size_t)BB*CO*NR*NN];// GEMM2 raw output                  64 MB
__device__ int   g_idx[BB*NN*3];
__device__ float g_wgt[BB*NN*3];
__device__ float g_sum1[CO], g_sumsq1[CO], g_s1[CO], g_t1[CO];
__device__ float g_sum2[CO], g_sumsq2[CO], g_s2[CO], g_t2[CO];

// ---------------- K0: zero the stat accumulators ----------------
__global__ void zero_stats_kernel() {
    int t = threadIdx.x;
    g_sum1[t] = 0.f; g_sumsq1[t] = 0.f;
    g_sum2[t] = 0.f; g_sumsq2[t] = 0.f;
}

// ---------------- K1: 3-NN + inverse-distance weights ----------------
__global__ void knn_kernel(const float* __restrict__ unknown,
                           const float* __restrict__ known) {
    __shared__ float skx[MM], sky[MM], skz[MM], skn[MM];
    int b = blockIdx.y;
    const float* kb = known + (size_t)b * MM * 3;
    for (int m = threadIdx.x; m < MM; m += blockDim.x) {
        float x = kb[m*3+0], y = kb[m*3+1], z = kb[m*3+2];
        skx[m] = x; sky[m] = y; skz[m] = z; skn[m] = x*x + y*y + z*z;
    }
    __syncthreads();

    int n = blockIdx.x * blockDim.x + threadIdx.x;
    const float* u = unknown + ((size_t)b * NN + n) * 3;
    float ux = u[0], uy = u[1], uz = u[2];
    float un2 = ux*ux + uy*uy + uz*uz;

    float d0 = FLT_MAX, d1 = FLT_MAX, d2 = FLT_MAX;
    int   i0 = 0, i1 = 0, i2 = 0;
    #pragma unroll 4
    for (int m = 0; m < MM; m++) {
        float d = un2 + skn[m] - 2.0f * (ux*skx[m] + uy*sky[m] + uz*skz[m]);
        if (d < d0)      { d2 = d1; i2 = i1; d1 = d0; i1 = i0; d0 = d; i0 = m; }
        else if (d < d1) { d2 = d1; i2 = i1; d1 = d;  i1 = m; }
        else if (d < d2) { d2 = d;  i2 = m; }
    }
    d0 = fmaxf(d0, 0.f); d1 = fmaxf(d1, 0.f); d2 = fmaxf(d2, 0.f);
    float r0 = 1.0f / (sqrtf(d0) + 1e-8f);
    float r1 = 1.0f / (sqrtf(d1) + 1e-8f);
    float r2 = 1.0f / (sqrtf(d2) + 1e-8f);
    float inv = 1.0f / (r0 + r1 + r2);
    size_t base = ((size_t)b * NN + n) * 3;
    g_wgt[base+0] = r0 * inv; g_wgt[base+1] = r1 * inv; g_wgt[base+2] = r2 * inv;
    g_idx[base+0] = i0; g_idx[base+1] = i1; g_idx[base+2] = i2;
}

// ---------------- K2: transpose known_feats (b,c,r,m) -> (b,r,m,c) ----------------
__global__ void transpose_kf_kernel(const float* __restrict__ kf) {
    __shared__ float tile[32][33];
    int br = blockIdx.z; int b = br >> 2; int r = br & 3;
    int m0 = blockIdx.x * 32, c0 = blockIdx.y * 32;
    int tx = threadIdx.x, ty = threadIdx.y;   // (32, 8)
    #pragma unroll
    for (int j = 0; j < 4; j++) {
        int c = c0 + ty + j*8;
        tile[ty + j*8][tx] = kf[(((size_t)b*CC + c)*NR + r)*MM + m0 + tx];
    }
    __syncthreads();
    #pragma unroll
    for (int j = 0; j < 4; j++) {
        int m = m0 + ty + j*8;
        g_Kt[(((size_t)b*NR + r)*MM + m)*CC + c0 + tx] = tile[tx][ty + j*8];
    }
}

// ---------------- K3: weighted interpolation -> g_interp (b,c,r,n) ----------------
// block: 256 threads, 32 positions of one (b,r); channels processed in chunks of 64
__global__ void interp_kernel() {
    __shared__ float sm[64*33];
    __shared__ float sw[32*3];
    __shared__ int   si[32*3];
    int b = blockIdx.z, r = blockIdx.y, n0 = blockIdx.x * 32;
    int tid = threadIdx.x, lane = tid & 31, w = tid >> 5;

    if (tid < 96) {
        size_t base = ((size_t)b*NN + n0) * 3 + tid;
        sw[tid] = g_wgt[base];
        si[tid] = g_idx[base];
    }
    __syncthreads();

    const float* Kt = g_Kt + ((size_t)b*NR + r) * MM * CC;
    int nl = w*4;   // this warp's first position

    for (int cc = 0; cc < CC; cc += 64) {
        #pragma unroll
        for (int pp = 0; pp < 4; pp++) {
            int p = nl + pp;
            float w0 = sw[p*3+0], w1 = sw[p*3+1], w2 = sw[p*3+2];
            const float* p0 = Kt + (size_t)si[p*3+0]*CC + cc;
            const float* p1 = Kt + (size_t)si[p*3+1]*CC + cc;
            const float* p2 = Kt + (size_t)si[p*3+2]*CC + cc;
            #pragma unroll
            for (int sub = 0; sub < 2; sub++) {
                int c = sub*32 + lane;
                float v = w0*p0[c] + w1*p1[c] + w2*p2[c];
                sm[c*33 + p] = v;
            }
        }
        __syncthreads();
        // coalesced write-out: 64 x 32 elements
        #pragma unroll
        for (int i = tid; i < 64*32; i += 256) {
            int cl = i >> 5, pl = i & 31;
            int c = cc + cl;
            g_interp[(((size_t)b*CC + c)*NR + r)*NN + n0 + pl] = sm[cl*33 + pl];
        }
        __syncthreads();
    }
}

// ---------------- GEMM helpers ----------------
#define TM 128
#define TN 128
#define BK 16

// GEMM1: y1[o, p] = sum_k W1[o,k] * x[k, p]   (x = concat(interp, unknow_feats))
// also accumulates per-channel sum/sumsq into g_sum1/g_sumsq1
__global__ __launch_bounds__(256, 2) void gemm1_kernel(
        const float* __restrict__ W1, const float* __restrict__ unknow_feats) {
    __shared__ float As[BK][TM];   // [k][o]
    __shared__ float Bs[BK][TN];   // [k][n]
    int slice = blockIdx.z; int b = slice >> 2, r = slice & 3;
    int o0 = blockIdx.y * TM, n0 = blockIdx.x * TN;
    int tid = threadIdx.x;
    int tx = tid & 15, ty = tid >> 4;

    float acc[8][8];
    #pragma unroll
    for (int i = 0; i < 8; i++)
        #pragma unroll
        for (int j = 0; j < 8; j++) acc[i][j] = 0.f;

    const int o_a  = tid >> 1;
    const int kq_a = tid & 1;
    const int rowb = tid >> 5;   // 0..7
    const int colb = tid & 31;   // float4 col index

    for (int k0 = 0; k0 < CIN; k0 += BK) {
        #pragma unroll
        for (int q = 0; q < 2; q++) {
            int kq = kq_a + q*2;
            float4 av = *(const float4*)&W1[(size_t)(o0 + o_a)*CIN + k0 + kq*4];
            As[kq*4+0][o_a] = av.x; As[kq*4+1][o_a] = av.y;
            As[kq*4+2][o_a] = av.z; As[kq*4+3][o_a] = av.w;
        }
        #pragma unroll
        for (int q = 0; q < 2; q++) {
            int krow = rowb + q*8;
            int k = k0 + krow;
            const float* src;
            if (k < CC) src = g_interp     + (((size_t)b*CC + k       )*NR + r)*NN;
            else        src = unknow_feats + (((size_t)b*CC + (k - CC))*NR + r)*NN;
            float4 bv = *(const float4*)&src[n0 + colb*4];
            *(float4*)&Bs[krow][colb*4] = bv;
        }
        __syncthreads();
        #pragma unroll
        for (int kk = 0; kk < BK; kk++) {
            float4 a0 = *(const float4*)&As[kk][ty*4];
            float4 a1 = *(const float4*)&As[kk][64 + ty*4];
            float4 b0 = *(const float4*)&Bs[kk][tx*4];
            float4 b1 = *(const float4*)&Bs[kk][64 + tx*4];
            float a[8] = {a0.x,a0.y,a0.z,a0.w,a1.x,a1.y,a1.z,a1.w};
            float bb[8] = {b0.x,b0.y,b0.z,b0.w,b1.x,b1.y,b1.z,b1.w};
            #pragma unroll
            for (int i = 0; i < 8; i++)
                #pragma unroll
                for (int j = 0; j < 8; j++)
                    acc[i][j] = fmaf(a[i], bb[j], acc[i][j]);
        }
        __syncthreads();
    }

    // epilogue: store y1 + per-channel stats
    #pragma unroll
    for (int ii = 0; ii < 8; ii++) {
        int o = o0 + ((ii < 4) ? (ty*4 + ii) : (64 + ty*4 + (ii - 4)));
        float* yrow = g_y1 + ((((size_t)b*CO + o)*NR + r)*NN) + n0;
        #pragma unroll
        for (int qj = 0; qj < 2; qj++) {
            float4 v = make_float4(acc[ii][qj*4+0], acc[ii][qj*4+1],
                                   acc[ii][qj*4+2], acc[ii][qj*4+3]);
            *(float4*)&yrow[qj*64 + tx*4] = v;
        }
        float s = 0.f, ss = 0.f;
        #pragma unroll
        for (int jj = 0; jj < 8; jj++) { float v = acc[ii][jj]; s += v; ss += v*v; }
        #pragma unroll
        for (int d = 8; d >= 1; d >>= 1) {
            s  += __shfl_xor_sync(0xffffffffu, s,  d);
            ss += __shfl_xor_sync(0xffffffffu, ss, d);
        }
        if (tx == 0) {
            atomicAdd(&g_sum1[o], s);
            atomicAdd(&g_sumsq1[o], ss);
        }
    }
}

// ---------------- stats: derive scale/shift for BN ----------------
__global__ void stats_kernel(const float* __restrict__ gamma,
                             const float* __restrict__ beta, int layer) {
    int c = threadIdx.x;
    float sum   = layer ? g_sum2[c]   : g_sum1[c];
    float sumsq = layer ? g_sumsq2[c] : g_sumsq1[c];
    const float invP = 1.0f / (float)PTOT;
    float mean = sum * invP;
    float var  = sumsq * invP - mean * mean;
    float s = gamma[c] * rsqrtf(var + 1e-5f);
    float t = beta[c] - mean * s;
    if (layer) { g_s2[c] = s; g_t2[c] = t; }
    else       { g_s1[c] = s; g_t1[c] = t; }
}

// GEMM2: y2[o,p] = sum_k W2[o,k] * relu(s1[k]*y1[k,p] + t1[k]); accumulate stats2
__global__ __launch_bounds__(256, 2) void gemm2_kernel(const float* __restrict__ W2) {
    __shared__ float As[BK][TM];
    __shared__ float Bs[BK][TN];
    int slice = blockIdx.z; int b = slice >> 2, r = slice & 3;
    int o0 = blockIdx.y * TM, n0 = blockIdx.x * TN;
    int tid = threadIdx.x;
    int tx = tid & 15, ty = tid >> 4;

    float acc[8][8];
    #pragma unroll
    for (int i = 0; i < 8; i++)
        #pragma unroll
        for (int j = 0; j < 8; j++) acc[i][j] = 0.f;

    const int o_a  = tid >> 1;
    const int kq_a = tid & 1;
    const int rowb = tid >> 5;
    const int colb = tid & 31;

    for (int k0 = 0; k0 < CO; k0 += BK) {
        #pragma unroll
        for (int q = 0; q < 2; q++) {
            int kq = kq_a + q*2;
            float4 av = *(const float4*)&W2[(size_t)(o0 + o_a)*CO + k0 + kq*4];
            As[kq*4+0][o_a] = av.x; As[kq*4+1][o_a] = av.y;
            As[kq*4+2][o_a] = av.z; As[kq*4+3][o_a] = av.w;
        }
        #pragma unroll
        for (int q = 0; q < 2; q++) {
            int krow = rowb + q*8;
            int k = k0 + krow;
            float s1v = g_s1[k], t1v = g_t1[k];
            const float* src = g_y1 + (((size_t)b*CO + k)*NR + r)*NN;
            float4 v = *(const float4*)&src[n0 + colb*4];
            v.x = fmaxf(fmaf(s1v, v.x, t1v), 0.f);
            v.y = fmaxf(fmaf(s1v, v.y, t1v), 0.f);
            v.z = fmaxf(fmaf(s1v, v.z, t1v), 0.f);
            v.w = fmaxf(fmaf(s1v, v.w, t1v), 0.f);
            *(float4*)&Bs[krow][colb*4] = v;
        }
        __syncthreads();
        #pragma unroll
        for (int kk = 0; kk < BK; kk++) {
            float4 a0 = *(const float4*)&As[kk][ty*4];
            float4 a1 = *(const float4*)&As[kk][64 + ty*4];
            float4 b0 = *(const float4*)&Bs[kk][tx*4];
            float4 b1 = *(const float4*)&Bs[kk][64 + tx*4];
            float a[8] = {a0.x,a0.y,a0.z,a0.w,a1.x,a1.y,a1.z,a1.w};
            float bb[8] = {b0.x,b0.y,b0.z,b0.w,b1.x,b1.y,b1.z,b1.w};
            #pragma unroll
            for (int i = 0; i < 8; i++)
                #pragma unroll
                for (int j = 0; j < 8; j++)
                    acc[i][j] = fmaf(a[i], bb[j], acc[i][j]);
        }
        __syncthreads();
    }

    #pragma unroll
    for (int ii = 0; ii < 8; ii++) {
        int o = o0 + ((ii < 4) ? (ty*4 + ii) : (64 + ty*4 + (ii - 4)));
        float* yrow = g_y2 + ((((size_t)b*CO + o)*NR + r)*NN) + n0;
        #pragma unroll
        for (int qj = 0; qj < 2; qj++) {
            float4 v = make_float4(acc[ii][qj*4+0], acc[ii][qj*4+1],
                                   acc[ii][qj*4+2], acc[ii][qj*4+3]);
            *(float4*)&yrow[qj*64 + tx*4] = v;
        }
        float s = 0.f, ss = 0.f;
        #pragma unroll
        for (int jj = 0; jj < 8; jj++) { float v = acc[ii][jj]; s += v; ss += v*v; }
        #pragma unroll
        for (int d = 8; d >= 1; d >>= 1) {
            s  += __shfl_xor_sync(0xffffffffu, s,  d);
            ss += __shfl_xor_sync(0xffffffffu, ss, d);
        }
        if (tx == 0) {
            atomicAdd(&g_sum2[o], s);
            atomicAdd(&g_sumsq2[o], ss);
        }
    }
}

// ---------------- final: BN2 + ReLU -> d_out ----------------
__global__ void final_kernel(float* __restrict__ out) {
    size_t i = (size_t)blockIdx.x * blockDim.x + threadIdx.x;
    size_t idx = i * 4;
    int o = (int)((idx >> 13) & 255);   // layout ((b*CO+o)*NR+r)*NN+n
    float s = g_s2[o], t = g_t2[o];
    float4 v = *(const float4*)&g_y2[idx];
    v.x = fmaxf(fmaf(s, v.x, t), 0.f);
    v.y = fmaxf(fmaf(s, v.y, t), 0.f);
    v.z = fmaxf(fmaf(s, v.z, t), 0.f);
    v.w = fmaxf(fmaf(s, v.w, t), 0.f);
    ((float4*)out)[i] = v;
}

// ---------------- launch ----------------
extern "C" void kernel_launch(void* const* d_in, const int* in_sizes, int n_in,
                              void* d_out, int out_size) {
    const float* unknown      = (const float*)d_in[0];
    const float* known        = (const float*)d_in[1];
    const float* unknow_feats = (const float*)d_in[2];
    const float* known_feats  = (const float*)d_in[3];
    const float* W1 = (const float*)d_in[4];
    const float* g1 = (const float*)d_in[5];
    const float* b1 = (const float*)d_in[6];
    const float* W2 = (const float*)d_in[7];
    const float* g2 = (const float*)d_in[8];
    const float* b2 = (const float*)d_in[9];
    float* out = (float*)d_out;

    zero_stats_kernel<<<1, 256>>>();
    knn_kernel<<<dim3(NN/256, BB), 256>>>(unknown, known);
    transpose_kf_kernel<<<dim3(MM/32, CC/32, BB*NR), dim3(32, 8)>>>(known_feats);
    interp_kernel<<<dim3(NN/32, NR, BB), 256>>>();
    gemm1_kernel<<<dim3(NN/TN, CO/TM, BB*NR), 256>>>(W1, unknow_feats);
    stats_kernel<<<1, 256>>>(g1, b1, 0);
    gemm2_kernel<<<dim3(NN/TN, CO/TM, BB*NR), 256>>>(W2);
    stats_kernel<<<1, 256>>>(g2, b2, 1);
    final_kernel<<<(int)(((size_t)BB*CO*NR*NN/4 + 255) / 256), 256>>>(out);
}

// round 2
// speedup vs baseline: 2.0079x; 2.0079x over previous
#include <cuda_runtime.h>
#include <cuda_bf16.h>
#include <float.h>
#include <stdint.h>

// Problem constants
#define BB   8
#define NN   2048
#define MM   512
#define CC   256      // channels per source (C1 = C2 = 256)
#define NR   4
#define CIN  512      // C1 + C2
#define CO   256      // output channels of both MLP layers
#define PTOT (BB*NR*NN)   // 65536 positions

// ---------------- scratch (device globals; no runtime allocation) ----------------
__device__ float g_Kt[BB*NR*MM*CC];        // known_feats transposed (b,r,m,c)  16 MB
__device__ float g_interp[BB*CC*NR*NN];    // interpolated feats (b,c,r,n)      64 MB
__device__ float g_y1[(size_t)BB*CO*NR*NN];// GEMM1 raw output                  64 MB
__device__ float g_y2[(size_t)BB*CO*NR*NN];// GEMM2 raw output                  64 MB
__device__ int   g_idx[BB*NN*3];
__device__ float g_wgt[BB*NN*3];
__device__ float g_sum1[CO], g_sumsq1[CO], g_s1[CO], g_t1[CO];
__device__ float g_sum2[CO], g_sumsq2[CO], g_s2[CO], g_t2[CO];

// ---------------- tf32 helpers ----------------
__device__ __forceinline__ uint32_t f2tf(float x) {
    uint32_t r;
    asm("cvt.rna.tf32.f32 %0, %1;" : "=r"(r) : "f"(x));
    return r;
}

__device__ __forceinline__ void mma_tf32(float* d, const uint32_t* a, const uint32_t* b) {
    asm volatile(
        "mma.sync.aligned.m16n8k8.row.col.f32.tf32.tf32.f32 "
        "{%0,%1,%2,%3}, {%4,%5,%6,%7}, {%8,%9}, {%0,%1,%2,%3};"
        : "+f"(d[0]), "+f"(d[1]), "+f"(d[2]), "+f"(d[3])
        : "r"(a[0]), "r"(a[1]), "r"(a[2]), "r"(a[3]), "r"(b[0]), "r"(b[1]));
}

// ---------------- K0: zero the stat accumulators ----------------
__global__ void zero_stats_kernel() {
    int t = threadIdx.x;
    g_sum1[t] = 0.f; g_sumsq1[t] = 0.f;
    g_sum2[t] = 0.f; g_sumsq2[t] = 0.f;
}

// ---------------- K1: 3-NN + inverse-distance weights ----------------
__global__ void knn_kernel(const float* __restrict__ unknown,
                           const float* __restrict__ known) {
    __shared__ float skx[MM], sky[MM], skz[MM], skn[MM];
    int b = blockIdx.y;
    const float* kb = known + (size_t)b * MM * 3;
    for (int m = threadIdx.x; m < MM; m += blockDim.x) {
        float x = kb[m*3+0], y = kb[m*3+1], z = kb[m*3+2];
        skx[m] = x; sky[m] = y; skz[m] = z; skn[m] = x*x + y*y + z*z;
    }
    __syncthreads();

    int n = blockIdx.x * blockDim.x + threadIdx.x;
    const float* u = unknown + ((size_t)b * NN + n) * 3;
    float ux = u[0], uy = u[1], uz = u[2];
    float un2 = ux*ux + uy*uy + uz*uz;

    float d0 = FLT_MAX, d1 = FLT_MAX, d2 = FLT_MAX;
    int   i0 = 0, i1 = 0, i2 = 0;
    #pragma unroll 4
    for (int m = 0; m < MM; m++) {
        float d = un2 + skn[m] - 2.0f * (ux*skx[m] + uy*sky[m] + uz*skz[m]);
        if (d < d0)      { d2 = d1; i2 = i1; d1 = d0; i1 = i0; d0 = d; i0 = m; }
        else if (d < d1) { d2 = d1; i2 = i1; d1 = d;  i1 = m; }
        else if (d < d2) { d2 = d;  i2 = m; }
    }
    d0 = fmaxf(d0, 0.f); d1 = fmaxf(d1, 0.f); d2 = fmaxf(d2, 0.f);
    float r0 = 1.0f / (sqrtf(d0) + 1e-8f);
    float r1 = 1.0f / (sqrtf(d1) + 1e-8f);
    float r2 = 1.0f / (sqrtf(d2) + 1e-8f);
    float inv = 1.0f / (r0 + r1 + r2);
    size_t base = ((size_t)b * NN + n) * 3;
    g_wgt[base+0] = r0 * inv; g_wgt[base+1] = r1 * inv; g_wgt[base+2] = r2 * inv;
    g_idx[base+0] = i0; g_idx[base+1] = i1; g_idx[base+2] = i2;
}

// ---------------- K2: transpose known_feats (b,c,r,m) -> (b,r,m,c) ----------------
__global__ void transpose_kf_kernel(const float* __restrict__ kf) {
    __shared__ float tile[32][33];
    int br = blockIdx.z; int b = br >> 2; int r = br & 3;
    int m0 = blockIdx.x * 32, c0 = blockIdx.y * 32;
    int tx = threadIdx.x, ty = threadIdx.y;   // (32, 8)
    #pragma unroll
    for (int j = 0; j < 4; j++) {
        int c = c0 + ty + j*8;
        tile[ty + j*8][tx] = kf[(((size_t)b*CC + c)*NR + r)*MM + m0 + tx];
    }
    __syncthreads();
    #pragma unroll
    for (int j = 0; j < 4; j++) {
        int m = m0 + ty + j*8;
        g_Kt[(((size_t)b*NR + r)*MM + m)*CC + c0 + tx] = tile[tx][ty + j*8];
    }
}

// ---------------- K3: weighted interpolation -> g_interp (b,c,r,n) ----------------
__global__ void interp_kernel() {
    __shared__ float sm[64*33];
    __shared__ float sw[32*3];
    __shared__ int   si[32*3];
    int b = blockIdx.z, r = blockIdx.y, n0 = blockIdx.x * 32;
    int tid = threadIdx.x, lane = tid & 31, w = tid >> 5;

    if (tid < 96) {
        size_t base = ((size_t)b*NN + n0) * 3 + tid;
        sw[tid] = g_wgt[base];
        si[tid] = g_idx[base];
    }
    __syncthreads();

    const float* Kt = g_Kt + ((size_t)b*NR + r) * MM * CC;
    int nl = w*4;

    for (int cc = 0; cc < CC; cc += 64) {
        #pragma unroll
        for (int pp = 0; pp < 4; pp++) {
            int p = nl + pp;
            float w0 = sw[p*3+0], w1 = sw[p*3+1], w2 = sw[p*3+2];
            const float* p0 = Kt + (size_t)si[p*3+0]*CC + cc;
            const float* p1 = Kt + (size_t)si[p*3+1]*CC + cc;
            const float* p2 = Kt + (size_t)si[p*3+2]*CC + cc;
            #pragma unroll
            for (int sub = 0; sub < 2; sub++) {
                int c = sub*32 + lane;
                float v = w0*p0[c] + w1*p1[c] + w2*p2[c];
                sm[c*33 + p] = v;
            }
        }
        __syncthreads();
        #pragma unroll
        for (int i = tid; i < 64*32; i += 256) {
            int cl = i >> 5, pl = i & 31;
            int c = cc + cl;
            g_interp[(((size_t)b*CC + c)*NR + r)*NN + n0 + pl] = sm[cl*33 + pl];
        }
        __syncthreads();
    }
}

// ---------------- tensor-core GEMM config ----------------
#define TM 128
#define TN 128
#define BK 32
#define SST 136   // smem row stride in words: (tig*8 + g) % 32 distinct -> conflict-free

// GEMM1: y1[o, p] = sum_k W1[o,k] * x[k, p]  (x = concat(interp, unknow_feats))
// + per-channel sum/sumsq accumulation
__global__ __launch_bounds__(256) void gemm1_kernel(
        const float* __restrict__ W1, const float* __restrict__ unknow_feats) {
    __shared__ uint32_t As[BK*SST];   // tf32 bits, [k][o]
    __shared__ uint32_t Bs[BK*SST];   // tf32 bits, [k][n]

    int slice = blockIdx.z; int b = slice >> 2, r = slice & 3;
    int o0 = blockIdx.y * TM, n0 = blockIdx.x * TN;
    int tid = threadIdx.x, lane = tid & 31, wid = tid >> 5;
    int g = lane >> 2, tig = lane & 3;
    int m0w = (wid & 1) * 64, n0w = (wid >> 1) * 32;

    float acc[4][4][4];
    #pragma unroll
    for (int i = 0; i < 4; i++)
        #pragma unroll
        for (int j = 0; j < 4; j++)
            #pragma unroll
            for (int e = 0; e < 4; e++) acc[i][j][e] = 0.f;

    // loader indices
    const int o_l = tid >> 1;          // 0..127
    const int kA  = (tid & 1) * 16;    // A k-offset base
    const int k_l = tid >> 5;          // 0..7 (B k row base)
    const int n4  = (tid & 31) * 4;    // B float4 col

    const float* Blo = g_interp      + ((size_t)b*CC*NR + r) * NN;  // + k*NR*NN
    const float* Bhi = unknow_feats  + ((size_t)b*CC*NR + r) * NN;

    float4 pa[4], pb[4];

    // prologue: load k-tile 0
    #pragma unroll
    for (int j = 0; j < 4; j++)
        pa[j] = *(const float4*)&W1[(size_t)(o0 + o_l)*CIN + kA + j*4];
    #pragma unroll
    for (int q = 0; q < 4; q++) {
        int k = k_l + q*8;
        const float* s = (k < CC) ? (Blo + (size_t)k * (NR*NN))
                                  : (Bhi + (size_t)(k - CC) * (NR*NN));
        pb[q] = *(const float4*)&s[n0 + n4];
    }

    for (int k0 = 0; k0 < CIN; k0 += BK) {
        // store (with cvt to tf32)
        #pragma unroll
        for (int j = 0; j < 4; j++) {
            const float* e = (const float*)&pa[j];
            #pragma unroll
            for (int t = 0; t < 4; t++)
                As[(kA + j*4 + t)*SST + o_l] = f2tf(e[t]);
        }
        #pragma unroll
        for (int q = 0; q < 4; q++) {
            uint4 v = make_uint4(f2tf(pb[q].x), f2tf(pb[q].y), f2tf(pb[q].z), f2tf(pb[q].w));
            *(uint4*)&Bs[(k_l + q*8)*SST + n4] = v;
        }
        __syncthreads();

        // prefetch next k-tile
        if (k0 + BK < CIN) {
            #pragma unroll
            for (int j = 0; j < 4; j++)
                pa[j] = *(const float4*)&W1[(size_t)(o0 + o_l)*CIN + (k0 + BK) + kA + j*4];
            #pragma unroll
            for (int q = 0; q < 4; q++) {
                int k = k0 + BK + k_l + q*8;
                const float* s = (k < CC) ? (Blo + (size_t)k * (NR*NN))
                                          : (Bhi + (size_t)(k - CC) * (NR*NN));
                pb[q] = *(const float4*)&s[n0 + n4];
            }
        }

        // compute
        #pragma unroll
        for (int kk = 0; kk < 4; kk++) {
            uint32_t af[4][4], bf[4][2];
            int kb = kk*8 + tig;
            #pragma unroll
            for (int mf = 0; mf < 4; mf++) {
                int m = m0w + mf*16 + g;
                af[mf][0] = As[kb*SST + m];
                af[mf][1] = As[kb*SST + m + 8];
                af[mf][2] = As[(kb+4)*SST + m];
                af[mf][3] = As[(kb+4)*SST + m + 8];
            }
            #pragma unroll
            for (int nf = 0; nf < 4; nf++) {
                int n = n0w + nf*8 + g;
                bf[nf][0] = Bs[kb*SST + n];
                bf[nf][1] = Bs[(kb+4)*SST + n];
            }
            #pragma unroll
            for (int mf = 0; mf < 4; mf++)
                #pragma unroll
                for (int nf = 0; nf < 4; nf++)
                    mma_tf32(acc[mf][nf], af[mf], bf[nf]);
        }
        __syncthreads();
    }

    // epilogue: store y1 + per-channel stats
    #pragma unroll
    for (int mf = 0; mf < 4; mf++) {
        int o = o0 + m0w + mf*16 + g;
        float sl = 0.f, ssl = 0.f, sh = 0.f, ssh = 0.f;
        #pragma unroll
        for (int nf = 0; nf < 4; nf++) {
            float* c = acc[mf][nf];
            float* base = g_y1 + (((size_t)b*CO + o)*NR + r)*NN + n0 + n0w + nf*8 + 2*tig;
            *(float2*)base = make_float2(c[0], c[1]);
            *(float2*)(base + (size_t)8*NR*NN) = make_float2(c[2], c[3]);
            sl += c[0] + c[1];  ssl += c[0]*c[0] + c[1]*c[1];
            sh += c[2] + c[3];  ssh += c[2]*c[2] + c[3]*c[3];
        }
        sl  += __shfl_xor_sync(0xffffffffu, sl, 1);  sl  += __shfl_xor_sync(0xffffffffu, sl, 2);
        ssl += __shfl_xor_sync(0xffffffffu, ssl, 1); ssl += __shfl_xor_sync(0xffffffffu, ssl, 2);
        sh  += __shfl_xor_sync(0xffffffffu, sh, 1);  sh  += __shfl_xor_sync(0xffffffffu, sh, 2);
        ssh += __shfl_xor_sync(0xffffffffu, ssh, 1); ssh += __shfl_xor_sync(0xffffffffu, ssh, 2);
        if (tig == 0) {
            atomicAdd(&g_sum1[o], sl);     atomicAdd(&g_sumsq1[o], ssl);
            atomicAdd(&g_sum1[o+8], sh);   atomicAdd(&g_sumsq1[o+8], ssh);
        }
    }
}

// ---------------- stats: derive scale/shift for BN ----------------
__global__ void stats_kernel(const float* __restrict__ gamma,
                             const float* __restrict__ beta, int layer) {
    int c = threadIdx.x;
    float sum   = layer ? g_sum2[c]   : g_sum1[c];
    float sumsq = layer ? g_sumsq2[c] : g_sumsq1[c];
    const float invP = 1.0f / (float)PTOT;
    float mean = sum * invP;
    float var  = sumsq * invP - mean * mean;
    float s = gamma[c] * rsqrtf(var + 1e-5f);
    float t = beta[c] - mean * s;
    if (layer) { g_s2[c] = s; g_t2[c] = t; }
    else       { g_s1[c] = s; g_t1[c] = t; }
}

// GEMM2: y2[o,p] = sum_k W2[o,k] * relu(s1[k]*y1[k,p] + t1[k]); accumulate stats2
__global__ __launch_bounds__(256) void gemm2_kernel(const float* __restrict__ W2) {
    __shared__ uint32_t As[BK*SST];
    __shared__ uint32_t Bs[BK*SST];

    int slice = blockIdx.z; int b = slice >> 2, r = slice & 3;
    int o0 = blockIdx.y * TM, n0 = blockIdx.x * TN;
    int tid = threadIdx.x, lane = tid & 31, wid = tid >> 5;
    int g = lane >> 2, tig = lane & 3;
    int m0w = (wid & 1) * 64, n0w = (wid >> 1) * 32;

    float acc[4][4][4];
    #pragma unroll
    for (int i = 0; i < 4; i++)
        #pragma unroll
        for (int j = 0; j < 4; j++)
            #pragma unroll
            for (int e = 0; e < 4; e++) acc[i][j][e] = 0.f;

    const int o_l = tid >> 1;
    const int kA  = (tid & 1) * 16;
    const int k_l = tid >> 5;
    const int n4  = (tid & 31) * 4;

    const float* Bsrc = g_y1 + ((size_t)b*CO*NR + r) * NN;  // + k*NR*NN

    float4 pa[4], pb[4];
    float  ps[4], pt[4];

    #pragma unroll
    for (int j = 0; j < 4; j++)
        pa[j] = *(const float4*)&W2[(size_t)(o0 + o_l)*CO + kA + j*4];
    #pragma unroll
    for (int q = 0; q < 4; q++) {
        int k = k_l + q*8;
        pb[q] = *(const float4*)&Bsrc[(size_t)k*(NR*NN) + n0 + n4];
        ps[q] = g_s1[k]; pt[q] = g_t1[k];
    }

    for (int k0 = 0; k0 < CO; k0 += BK) {
        #pragma unroll
        for (int j = 0; j < 4; j++) {
            const float* e = (const float*)&pa[j];
            #pragma unroll
            for (int t = 0; t < 4; t++)
                As[(kA + j*4 + t)*SST + o_l] = f2tf(e[t]);
        }
        #pragma unroll
        for (int q = 0; q < 4; q++) {
            float s1 = ps[q], t1 = pt[q];
            float x0 = fmaxf(fmaf(s1, pb[q].x, t1), 0.f);
            float x1 = fmaxf(fmaf(s1, pb[q].y, t1), 0.f);
            float x2 = fmaxf(fmaf(s1, pb[q].z, t1), 0.f);
            float x3 = fmaxf(fmaf(s1, pb[q].w, t1), 0.f);
            uint4 v = make_uint4(f2tf(x0), f2tf(x1), f2tf(x2), f2tf(x3));
            *(uint4*)&Bs[(k_l + q*8)*SST + n4] = v;
        }
        __syncthreads();

        if (k0 + BK < CO) {
            #pragma unroll
            for (int j = 0; j < 4; j++)
                pa[j] = *(const float4*)&W2[(size_t)(o0 + o_l)*CO + (k0 + BK) + kA + j*4];
            #pragma unroll
            for (int q = 0; q < 4; q++) {
                int k = k0 + BK + k_l + q*8;
                pb[q] = *(const float4*)&Bsrc[(size_t)k*(NR*NN) + n0 + n4];
                ps[q] = g_s1[k]; pt[q] = g_t1[k];
            }
        }

        #pragma unroll
        for (int kk = 0; kk < 4; kk++) {
            uint32_t af[4][4], bf[4][2];
            int kb = kk*8 + tig;
            #pragma unroll
            for (int mf = 0; mf < 4; mf++) {
                int m = m0w + mf*16 + g;
                af[mf][0] = As[kb*SST + m];
                af[mf][1] = As[kb*SST + m + 8];
                af[mf][2] = As[(kb+4)*SST + m];
                af[mf][3] = As[(kb+4)*SST + m + 8];
            }
            #pragma unroll
            for (int nf = 0; nf < 4; nf++) {
                int n = n0w + nf*8 + g;
                bf[nf][0] = Bs[kb*SST + n];
                bf[nf][1] = Bs[(kb+4)*SST + n];
            }
            #pragma unroll
            for (int mf = 0; mf < 4; mf++)
                #pragma unroll
                for (int nf = 0; nf < 4; nf++)
                    mma_tf32(acc[mf][nf], af[mf], bf[nf]);
        }
        __syncthreads();
    }

    #pragma unroll
    for (int mf = 0; mf < 4; mf++) {
        int o = o0 + m0w + mf*16 + g;
        float sl = 0.f, ssl = 0.f, sh = 0.f, ssh = 0.f;
        #pragma unroll
        for (int nf = 0; nf < 4; nf++) {
            float* c = acc[mf][nf];
            float* base = g_y2 + (((size_t)b*CO + o)*NR + r)*NN + n0 + n0w + nf*8 + 2*tig;
            *(float2*)base = make_float2(c[0], c[1]);
            *(float2*)(base + (size_t)8*NR*NN) = make_float2(c[2], c[3]);
            sl += c[0] + c[1];  ssl += c[0]*c[0] + c[1]*c[1];
            sh += c[2] + c[3];  ssh += c[2]*c[2] + c[3]*c[3];
        }
        sl  += __shfl_xor_sync(0xffffffffu, sl, 1);  sl  += __shfl_xor_sync(0xffffffffu, sl, 2);
        ssl += __shfl_xor_sync(0xffffffffu, ssl, 1); ssl += __shfl_xor_sync(0xffffffffu, ssl, 2);
        sh  += __shfl_xor_sync(0xffffffffu, sh, 1);  sh  += __shfl_xor_sync(0xffffffffu, sh, 2);
        ssh += __shfl_xor_sync(0xffffffffu, ssh, 1); ssh += __shfl_xor_sync(0xffffffffu, ssh, 2);
        if (tig == 0) {
            atomicAdd(&g_sum2[o], sl);     atomicAdd(&g_sumsq2[o], ssl);
            atomicAdd(&g_sum2[o+8], sh);   atomicAdd(&g_sumsq2[o+8], ssh);
        }
    }
}

// ---------------- final: BN2 + ReLU -> d_out ----------------
__global__ void final_kernel(float* __restrict__ out) {
    size_t i = (size_t)blockIdx.x * blockDim.x + threadIdx.x;
    size_t idx = i * 4;
    int o = (int)((idx >> 13) & 255);   // layout ((b*CO+o)*NR+r)*NN+n
    float s = g_s2[o], t = g_t2[o];
    float4 v = *(const float4*)&g_y2[idx];
    v.x = fmaxf(fmaf(s, v.x, t), 0.f);
    v.y = fmaxf(fmaf(s, v.y, t), 0.f);
    v.z = fmaxf(fmaf(s, v.z, t), 0.f);
    v.w = fmaxf(fmaf(s, v.w, t), 0.f);
    ((float4*)out)[i] = v;
}

// ---------------- launch ----------------
extern "C" void kernel_launch(void* const* d_in, const int* in_sizes, int n_in,
                              void* d_out, int out_size) {
    const float* unknown      = (const float*)d_in[0];
    const float* known        = (const float*)d_in[1];
    const float* unknow_feats = (const float*)d_in[2];
    const float* known_feats  = (const float*)d_in[3];
    const float* W1 = (const float*)d_in[4];
    const float* g1 = (const float*)d_in[5];
    const float* b1 = (const float*)d_in[6];
    const float* W2 = (const float*)d_in[7];
    const float* g2 = (const float*)d_in[8];
    const float* b2 = (const float*)d_in[9];
    float* out = (float*)d_out;

    zero_stats_kernel<<<1, 256>>>();
    knn_kernel<<<dim3(NN/256, BB), 256>>>(unknown, known);
    transpose_kf_kernel<<<dim3(MM/32, CC/32, BB*NR), dim3(32, 8)>>>(known_feats);
    interp_kernel<<<dim3(NN/32, NR, BB), 256>>>();
    gemm1_kernel<<<dim3(NN/TN, CO/TM, BB*NR), 256>>>(W1, unknow_feats);
    stats_kernel<<<1, 256>>>(g1, b1, 0);
    gemm2_kernel<<<dim3(NN/TN, CO/TM, BB*NR), 256>>>(W2);
    stats_kernel<<<1, 256>>>(g2, b2, 1);
    final_kernel<<<(int)(((size_t)BB*CO*NR*NN/4 + 255) / 256), 256>>>(out);
}

// round 4
// speedup vs baseline: 2.1632x; 1.0773x over previous
#include <cuda_runtime.h>
#include <cuda_bf16.h>
#include <float.h>
#include <stdint.h>

// Problem constants
#define BB   8
#define NN   2048
#define MM   512
#define CC   256      // channels per source (C1 = C2 = 256)
#define NR   4
#define CIN  512      // C1 + C2
#define CO   256      // output channels of both MLP layers
#define PTOT (BB*NR*NN)   // 65536 positions

// ---------------- scratch (device globals; no runtime allocation) ----------------
__device__ float g_Z [(size_t)BB*NR*CO*MM];   // Z = W1a @ known_feats, (slice, o, m)  16 MB
__device__ float g_Zt[(size_t)BB*NR*MM*CO];   // Z transposed (slice, m, o)            16 MB
__device__ float g_y1[(size_t)BB*CO*NR*NN];   // GEMM1 raw output                      64 MB
__device__ float g_y2[(size_t)BB*CO*NR*NN];   // GEMM2 raw output                      64 MB
__device__ int   g_idx[BB*NN*3];
__device__ float g_wgt[BB*NN*3];
__device__ float g_sum1[CO], g_sumsq1[CO], g_s1[CO], g_t1[CO];
__device__ float g_sum2[CO], g_sumsq2[CO], g_s2[CO], g_t2[CO];

// ---------------- tf32 helpers ----------------
__device__ __forceinline__ uint32_t f2tf(float x) {
    uint32_t r;
    asm("cvt.rna.tf32.f32 %0, %1;" : "=r"(r) : "f"(x));
    return r;
}

__device__ __forceinline__ void mma_tf32(float* d, const uint32_t* a, const uint32_t* b) {
    asm volatile(
        "mma.sync.aligned.m16n8k8.row.col.f32.tf32.tf32.f32 "
        "{%0,%1,%2,%3}, {%4,%5,%6,%7}, {%8,%9}, {%0,%1,%2,%3};"
        : "+f"(d[0]), "+f"(d[1]), "+f"(d[2]), "+f"(d[3])
        : "r"(a[0]), "r"(a[1]), "r"(a[2]), "r"(a[3]), "r"(b[0]), "r"(b[1]));
}

// ---------------- K0: zero the stat accumulators ----------------
__global__ void zero_stats_kernel() {
    int t = threadIdx.x;
    g_sum1[t] = 0.f; g_sumsq1[t] = 0.f;
    g_sum2[t] = 0.f; g_sumsq2[t] = 0.f;
}

// ---------------- K1: 3-NN + inverse-distance weights ----------------
__global__ void knn_kernel(const float* __restrict__ unknown,
                           const float* __restrict__ known) {
    __shared__ float skx[MM], sky[MM], skz[MM], skn[MM];
    int b = blockIdx.y;
    const float* kb = known + (size_t)b * MM * 3;
    for (int m = threadIdx.x; m < MM; m += blockDim.x) {
        float x = kb[m*3+0], y = kb[m*3+1], z = kb[m*3+2];
        skx[m] = x; sky[m] = y; skz[m] = z; skn[m] = x*x + y*y + z*z;
    }
    __syncthreads();

    int n = blockIdx.x * blockDim.x + threadIdx.x;
    const float* u = unknown + ((size_t)b * NN + n) * 3;
    float ux = u[0], uy = u[1], uz = u[2];
    float un2 = ux*ux + uy*uy + uz*uz;

    float d0 = FLT_MAX, d1 = FLT_MAX, d2 = FLT_MAX;
    int   i0 = 0, i1 = 0, i2 = 0;
    #pragma unroll 4
    for (int m = 0; m < MM; m++) {
        float d = un2 + skn[m] - 2.0f * (ux*skx[m] + uy*sky[m] + uz*skz[m]);
        if (d < d0)      { d2 = d1; i2 = i1; d1 = d0; i1 = i0; d0 = d; i0 = m; }
        else if (d < d1) { d2 = d1; i2 = i1; d1 = d;  i1 = m; }
        else if (d < d2) { d2 = d;  i2 = m; }
    }
    d0 = fmaxf(d0, 0.f); d1 = fmaxf(d1, 0.f); d2 = fmaxf(d2, 0.f);
    float r0 = 1.0f / (sqrtf(d0) + 1e-8f);
    float r1 = 1.0f / (sqrtf(d1) + 1e-8f);
    float r2 = 1.0f / (sqrtf(d2) + 1e-8f);
    float inv = 1.0f / (r0 + r1 + r2);
    size_t base = ((size_t)b * NN + n) * 3;
    g_wgt[base+0] = r0 * inv; g_wgt[base+1] = r1 * inv; g_wgt[base+2] = r2 * inv;
    g_idx[base+0] = i0; g_idx[base+1] = i1; g_idx[base+2] = i2;
}

// ---------------- tensor-core GEMM config ----------------
#define TM 128
#define TN 128
#define BK 32
#define SST 136   // smem row stride in words -> conflict-free fragment loads

// ---------------- K2: Z = W1a @ known_feats  per slice (o x m) ----------------
__global__ __launch_bounds__(256) void zgemm_kernel(
        const float* __restrict__ W1, const float* __restrict__ kf) {
    __shared__ uint32_t As[BK*SST];
    __shared__ uint32_t Bs[BK*SST];

    int slice = blockIdx.z; int b = slice >> 2, r = slice & 3;
    int o0 = blockIdx.y * TM, m0t = blockIdx.x * TN;
    int tid = threadIdx.x, lane = tid & 31, wid = tid >> 5;
    int g = lane >> 2, tig = lane & 3;
    int m0w = (wid & 1) * 64, n0w = (wid >> 1) * 32;

    float acc[4][4][4];
    #pragma unroll
    for (int i = 0; i < 4; i++)
        #pragma unroll
        for (int j = 0; j < 4; j++)
            #pragma unroll
            for (int e = 0; e < 4; e++) acc[i][j][e] = 0.f;

    const int o_l = tid >> 1;
    const int kA  = (tid & 1) * 16;
    const int k_l = tid >> 5;
    const int n4  = (tid & 31) * 4;

    const float* Bsrc = kf + ((size_t)b*CC*NR + r) * MM;   // + k*NR*MM

    float4 pa[4], pb[4];
    #pragma unroll
    for (int j = 0; j < 4; j++)
        pa[j] = *(const float4*)&W1[(size_t)(o0 + o_l)*CIN + kA + j*4];
    #pragma unroll
    for (int q = 0; q < 4; q++) {
        int k = k_l + q*8;
        pb[q] = *(const float4*)&Bsrc[(size_t)k*(NR*MM) + m0t + n4];
    }

    for (int k0 = 0; k0 < CC; k0 += BK) {
        #pragma unroll
        for (int j = 0; j < 4; j++) {
            const float* e = (const float*)&pa[j];
            #pragma unroll
            for (int t = 0; t < 4; t++)
                As[(kA + j*4 + t)*SST + o_l] = f2tf(e[t]);
        }
        #pragma unroll
        for (int q = 0; q < 4; q++) {
            uint4 v = make_uint4(f2tf(pb[q].x), f2tf(pb[q].y), f2tf(pb[q].z), f2tf(pb[q].w));
            *(uint4*)&Bs[(k_l + q*8)*SST + n4] = v;
        }
        __syncthreads();

        if (k0 + BK < CC) {
            #pragma unroll
            for (int j = 0; j < 4; j++)
                pa[j] = *(const float4*)&W1[(size_t)(o0 + o_l)*CIN + (k0 + BK) + kA + j*4];
            #pragma unroll
            for (int q = 0; q < 4; q++) {
                int k = k0 + BK + k_l + q*8;
                pb[q] = *(const float4*)&Bsrc[(size_t)k*(NR*MM) + m0t + n4];
            }
        }

        #pragma unroll
        for (int kk = 0; kk < 4; kk++) {
            uint32_t af[4][4], bf[4][2];
            int kb = kk*8 + tig;
            #pragma unroll
            for (int mf = 0; mf < 4; mf++) {
                int m = m0w + mf*16 + g;
                af[mf][0] = As[kb*SST + m];
                af[mf][1] = As[kb*SST + m + 8];
                af[mf][2] = As[(kb+4)*SST + m];
                af[mf][3] = As[(kb+4)*SST + m + 8];
            }
            #pragma unroll
            for (int nf = 0; nf < 4; nf++) {
                int n = n0w + nf*8 + g;
                bf[nf][0] = Bs[kb*SST + n];
                bf[nf][1] = Bs[(kb+4)*SST + n];
            }
            #pragma unroll
            for (int mf = 0; mf < 4; mf++)
                #pragma unroll
                for (int nf = 0; nf < 4; nf++)
                    mma_tf32(acc[mf][nf], af[mf], bf[nf]);
        }
        __syncthreads();
    }

    float* Zs = g_Z + (size_t)slice * CO * MM;
    #pragma unroll
    for (int mf = 0; mf < 4; mf++) {
        int o = o0 + m0w + mf*16 + g;
        #pragma unroll
        for (int nf = 0; nf < 4; nf++) {
            float* c = acc[mf][nf];
            float* base = Zs + (size_t)o*MM + m0t + n0w + nf*8 + 2*tig;
            *(float2*)base = make_float2(c[0], c[1]);
            *(float2*)(base + (size_t)8*MM) = make_float2(c[2], c[3]);
        }
    }
}

// ---------------- K3: transpose Z (o, m) -> Zt (m, o) per slice ----------------
__global__ void transpose_z_kernel() {
    __shared__ float tile[32][33];
    int slice = blockIdx.z;
    int m0 = blockIdx.x * 32, o0 = blockIdx.y * 32;
    const float* Z  = g_Z  + (size_t)slice * CO * MM;
    float*       Zt = g_Zt + (size_t)slice * CO * MM;
    int tx = threadIdx.x, ty = threadIdx.y;   // (32, 8)
    #pragma unroll
    for (int j = 0; j < 4; j++)
        tile[ty + j*8][tx] = Z[(size_t)(o0 + ty + j*8)*MM + m0 + tx];
    __syncthreads();
    #pragma unroll
    for (int j = 0; j < 4; j++)
        Zt[(size_t)(m0 + ty + j*8)*CO + o0 + tx] = tile[tx][ty + j*8];
}

// ---------------- K4: GEMM1' : y1 = W1b @ uf + gather-interp(Zt) ----------------
__global__ __launch_bounds__(256) void gemm1_kernel(
        const float* __restrict__ W1, const float* __restrict__ unknow_feats) {
    __shared__ uint32_t As[BK*SST];
    __shared__ uint32_t Bs[BK*SST];
    __shared__ float sw[TN*3];
    __shared__ int   si[TN*3];

    int slice = blockIdx.z; int b = slice >> 2, r = slice & 3;
    int o0 = blockIdx.y * TM, n0 = blockIdx.x * TN;
    int tid = threadIdx.x, lane = tid & 31, wid = tid >> 5;
    int g = lane >> 2, tig = lane & 3;
    int m0w = (wid & 1) * 64, n0w = (wid >> 1) * 32;

    // stage interpolation weights/indices for this CTA's 128 positions
    for (int i = tid; i < TN*3; i += 256) {
        size_t base = ((size_t)b*NN + n0) * 3 + i;
        sw[i] = g_wgt[base];
        si[i] = g_idx[base];
    }

    float acc[4][4][4];
    #pragma unroll
    for (int i = 0; i < 4; i++)
        #pragma unroll
        for (int j = 0; j < 4; j++)
            #pragma unroll
            for (int e = 0; e < 4; e++) acc[i][j][e] = 0.f;

    const int o_l = tid >> 1;
    const int kA  = (tid & 1) * 16;
    const int k_l = tid >> 5;
    const int n4  = (tid & 31) * 4;

    const float* Bsrc = unknow_feats + ((size_t)b*CC*NR + r) * NN;   // + k*NR*NN

    float4 pa[4], pb[4];
    #pragma unroll
    for (int j = 0; j < 4; j++)
        pa[j] = *(const float4*)&W1[(size_t)(o0 + o_l)*CIN + CC + kA + j*4];
    #pragma unroll
    for (int q = 0; q < 4; q++) {
        int k = k_l + q*8;
        pb[q] = *(const float4*)&Bsrc[(size_t)k*(NR*NN) + n0 + n4];
    }

    for (int k0 = 0; k0 < CC; k0 += BK) {
        #pragma unroll
        for (int j = 0; j < 4; j++) {
            const float* e = (const float*)&pa[j];
            #pragma unroll
            for (int t = 0; t < 4; t++)
                As[(kA + j*4 + t)*SST + o_l] = f2tf(e[t]);
        }
        #pragma unroll
        for (int q = 0; q < 4; q++) {
            uint4 v = make_uint4(f2tf(pb[q].x), f2tf(pb[q].y), f2tf(pb[q].z), f2tf(pb[q].w));
            *(uint4*)&Bs[(k_l + q*8)*SST + n4] = v;
        }
        __syncthreads();

        if (k0 + BK < CC) {
            #pragma unroll
            for (int j = 0; j < 4; j++)
                pa[j] = *(const float4*)&W1[(size_t)(o0 + o_l)*CIN + CC + (k0 + BK) + kA + j*4];
            #pragma unroll
            for (int q = 0; q < 4; q++) {
                int k = k0 + BK + k_l + q*8;
                pb[q] = *(const float4*)&Bsrc[(size_t)k*(NR*NN) + n0 + n4];
            }
        }

        #pragma unroll
        for (int kk = 0; kk < 4; kk++) {
            uint32_t af[4][4], bf[4][2];
            int kb = kk*8 + tig;
            #pragma unroll
            for (int mf = 0; mf < 4; mf++) {
                int m = m0w + mf*16 + g;
                af[mf][0] = As[kb*SST + m];
                af[mf][1] = As[kb*SST + m + 8];
                af[mf][2] = As[(kb+4)*SST + m];
                af[mf][3] = As[(kb+4)*SST + m + 8];
            }
            #pragma unroll
            for (int nf = 0; nf < 4; nf++) {
                int n = n0w + nf*8 + g;
                bf[nf][0] = Bs[kb*SST + n];
                bf[nf][1] = Bs[(kb+4)*SST + n];
            }
            #pragma unroll
            for (int mf = 0; mf < 4; mf++)
                #pragma unroll
                for (int nf = 0; nf < 4; nf++)
                    mma_tf32(acc[mf][nf], af[mf], bf[nf]);
        }
        __syncthreads();
    }

    // ---- gather-interp: acc += sum_j w_j * Zt[m_j][o] ----
    const float* Zts = g_Zt + (size_t)slice * CO * MM;
    #pragma unroll
    for (int nf = 0; nf < 4; nf++) {
        #pragma unroll
        for (int e = 0; e < 2; e++) {
            int pl = n0w + nf*8 + 2*tig + e;     // local position 0..127
            float w0 = sw[pl*3+0], w1 = sw[pl*3+1], w2 = sw[pl*3+2];
            const float* r0 = Zts + (size_t)si[pl*3+0]*CO + o0;
            const float* r1 = Zts + (size_t)si[pl*3+1]*CO + o0;
            const float* r2 = Zts + (size_t)si[pl*3+2]*CO + o0;
            #pragma unroll
            for (int mf = 0; mf < 4; mf++) {
                int o = m0w + mf*16 + g;
                acc[mf][nf][e]   += w0*r0[o]   + w1*r1[o]   + w2*r2[o];
                acc[mf][nf][2+e] += w0*r0[o+8] + w1*r1[o+8] + w2*r2[o+8];
            }
        }
    }

    // epilogue: store y1 + per-channel stats
    #pragma unroll
    for (int mf = 0; mf < 4; mf++) {
        int o = o0 + m0w + mf*16 + g;
        float sl = 0.f, ssl = 0.f, sh = 0.f, ssh = 0.f;
        #pragma unroll
        for (int nf = 0; nf < 4; nf++) {
            float* c = acc[mf][nf];
            float* base = g_y1 + (((size_t)b*CO + o)*NR + r)*NN + n0 + n0w + nf*8 + 2*tig;
            *(float2*)base = make_float2(c[0], c[1]);
            *(float2*)(base + (size_t)8*NR*NN) = make_float2(c[2], c[3]);
            sl += c[0] + c[1];  ssl += c[0]*c[0] + c[1]*c[1];
            sh += c[2] + c[3];  ssh += c[2]*c[2] + c[3]*c[3];
        }
        sl  += __shfl_xor_sync(0xffffffffu, sl, 1);  sl  += __shfl_xor_sync(0xffffffffu, sl, 2);
        ssl += __shfl_xor_sync(0xffffffffu, ssl, 1); ssl += __shfl_xor_sync(0xffffffffu, ssl, 2);
        sh  += __shfl_xor_sync(0xffffffffu, sh, 1);  sh  += __shfl_xor_sync(0xffffffffu, sh, 2);
        ssh += __shfl_xor_sync(0xffffffffu, ssh, 1); ssh += __shfl_xor_sync(0xffffffffu, ssh, 2);
        if (tig == 0) {
            atomicAdd(&g_sum1[o], sl);     atomicAdd(&g_sumsq1[o], ssl);
            atomicAdd(&g_sum1[o+8], sh);   atomicAdd(&g_sumsq1[o+8], ssh);
        }
    }
}

// ---------------- stats: derive scale/shift for BN ----------------
__global__ void stats_kernel(const float* __restrict__ gamma,
                             const float* __restrict__ beta, int layer) {
    int c = threadIdx.x;
    float sum   = layer ? g_sum2[c]   : g_sum1[c];
    float sumsq = layer ? g_sumsq2[c] : g_sumsq1[c];
    const float invP = 1.0f / (float)PTOT;
    float mean = sum * invP;
    float var  = sumsq * invP - mean * mean;
    float s = gamma[c] * rsqrtf(var + 1e-5f);
    float t = beta[c] - mean * s;
    if (layer) { g_s2[c] = s; g_t2[c] = t; }
    else       { g_s1[c] = s; g_t1[c] = t; }
}

// GEMM2: y2[o,p] = sum_k W2[o,k] * relu(s1[k]*y1[k,p] + t1[k]); accumulate stats2
__global__ __launch_bounds__(256) void gemm2_kernel(const float* __restrict__ W2) {
    __shared__ uint32_t As[BK*SST];
    __shared__ uint32_t Bs[BK*SST];

    int slice = blockIdx.z; int b = slice >> 2, r = slice & 3;
    int o0 = blockIdx.y * TM, n0 = blockIdx.x * TN;
    int tid = threadIdx.x, lane = tid & 31, wid = tid >> 5;
    int g = lane >> 2, tig = lane & 3;
    int m0w = (wid & 1) * 64, n0w = (wid >> 1) * 32;

    float acc[4][4][4];
    #pragma unroll
    for (int i = 0; i < 4; i++)
        #pragma unroll
        for (int j = 0; j < 4; j++)
            #pragma unroll
            for (int e = 0; e < 4; e++) acc[i][j][e] = 0.f;

    const int o_l = tid >> 1;
    const int kA  = (tid & 1) * 16;
    const int k_l = tid >> 5;
    const int n4  = (tid & 31) * 4;

    const float* Bsrc = g_y1 + ((size_t)b*CO*NR + r) * NN;

    float4 pa[4], pb[4];
    float  ps[4], pt[4];

    #pragma unroll
    for (int j = 0; j < 4; j++)
        pa[j] = *(const float4*)&W2[(size_t)(o0 + o_l)*CO + kA + j*4];
    #pragma unroll
    for (int q = 0; q < 4; q++) {
        int k = k_l + q*8;
        pb[q] = *(const float4*)&Bsrc[(size_t)k*(NR*NN) + n0 + n4];
        ps[q] = g_s1[k]; pt[q] = g_t1[k];
    }

    for (int k0 = 0; k0 < CO; k0 += BK) {
        #pragma unroll
        for (int j = 0; j < 4; j++) {
            const float* e = (const float*)&pa[j];
            #pragma unroll
            for (int t = 0; t < 4; t++)
                As[(kA + j*4 + t)*SST + o_l] = f2tf(e[t]);
        }
        #pragma unroll
        for (int q = 0; q < 4; q++) {
            float s1 = ps[q], t1 = pt[q];
            float x0 = fmaxf(fmaf(s1, pb[q].x, t1), 0.f);
            float x1 = fmaxf(fmaf(s1, pb[q].y, t1), 0.f);
            float x2 = fmaxf(fmaf(s1, pb[q].z, t1), 0.f);
            float x3 = fmaxf(fmaf(s1, pb[q].w, t1), 0.f);
            uint4 v = make_uint4(f2tf(x0), f2tf(x1), f2tf(x2), f2tf(x3));
            *(uint4*)&Bs[(k_l + q*8)*SST + n4] = v;
        }
        __syncthreads();

        if (k0 + BK < CO) {
            #pragma unroll
            for (int j = 0; j < 4; j++)
                pa[j] = *(const float4*)&W2[(size_t)(o0 + o_l)*CO + (k0 + BK) + kA + j*4];
            #pragma unroll
            for (int q = 0; q < 4; q++) {
                int k = k0 + BK + k_l + q*8;
                pb[q] = *(const float4*)&Bsrc[(size_t)k*(NR*NN) + n0 + n4];
                ps[q] = g_s1[k]; pt[q] = g_t1[k];
            }
        }

        #pragma unroll
        for (int kk = 0; kk < 4; kk++) {
            uint32_t af[4][4], bf[4][2];
            int kb = kk*8 + tig;
            #pragma unroll
            for (int mf = 0; mf < 4; mf++) {
                int m = m0w + mf*16 + g;
                af[mf][0] = As[kb*SST + m];
                af[mf][1] = As[kb*SST + m + 8];
                af[mf][2] = As[(kb+4)*SST + m];
                af[mf][3] = As[(kb+4)*SST + m + 8];
            }
            #pragma unroll
            for (int nf = 0; nf < 4; nf++) {
                int n = n0w + nf*8 + g;
                bf[nf][0] = Bs[kb*SST + n];
                bf[nf][1] = Bs[(kb+4)*SST + n];
            }
            #pragma unroll
            for (int mf = 0; mf < 4; mf++)
                #pragma unroll
                for (int nf = 0; nf < 4; nf++)
                    mma_tf32(acc[mf][nf], af[mf], bf[nf]);
        }
        __syncthreads();
    }

    #pragma unroll
    for (int mf = 0; mf < 4; mf++) {
        int o = o0 + m0w + mf*16 + g;
        float sl = 0.f, ssl = 0.f, sh = 0.f, ssh = 0.f;
        #pragma unroll
        for (int nf = 0; nf < 4; nf++) {
            float* c = acc[mf][nf];
            float* base = g_y2 + (((size_t)b*CO + o)*NR + r)*NN + n0 + n0w + nf*8 + 2*tig;
            *(float2*)base = make_float2(c[0], c[1]);
            *(float2*)(base + (size_t)8*NR*NN) = make_float2(c[2], c[3]);
            sl += c[0] + c[1];  ssl += c[0]*c[0] + c[1]*c[1];
            sh += c[2] + c[3];  ssh += c[2]*c[2] + c[3]*c[3];
        }
        sl  += __shfl_xor_sync(0xffffffffu, sl, 1);  sl  += __shfl_xor_sync(0xffffffffu, sl, 2);
        ssl += __shfl_xor_sync(0xffffffffu, ssl, 1); ssl += __shfl_xor_sync(0xffffffffu, ssl, 2);
        sh  += __shfl_xor_sync(0xffffffffu, sh, 1);  sh  += __shfl_xor_sync(0xffffffffu, sh, 2);
        ssh += __shfl_xor_sync(0xffffffffu, ssh, 1); ssh += __shfl_xor_sync(0xffffffffu, ssh, 2);
        if (tig == 0) {
            atomicAdd(&g_sum2[o], sl);     atomicAdd(&g_sumsq2[o], ssl);
            atomicAdd(&g_sum2[o+8], sh);   atomicAdd(&g_sumsq2[o+8], ssh);
        }
    }
}

// ---------------- final: BN2 + ReLU -> d_out ----------------
__global__ void final_kernel(float* __restrict__ out) {
    size_t i = (size_t)blockIdx.x * blockDim.x + threadIdx.x;
    size_t idx = i * 4;
    int o = (int)((idx >> 13) & 255);   // layout ((b*CO+o)*NR+r)*NN+n
    float s = g_s2[o], t = g_t2[o];
    float4 v = *(const float4*)&g_y2[idx];
    v.x = fmaxf(fmaf(s, v.x, t), 0.f);
    v.y = fmaxf(fmaf(s, v.y, t), 0.f);
    v.z = fmaxf(fmaf(s, v.z, t), 0.f);
    v.w = fmaxf(fmaf(s, v.w, t), 0.f);
    ((float4*)out)[i] = v;
}

// ---------------- launch ----------------
extern "C" void kernel_launch(void* const* d_in, const int* in_sizes, int n_in,
                              void* d_out, int out_size) {
    const float* unknown      = (const float*)d_in[0];
    const float* known        = (const float*)d_in[1];
    const float* unknow_feats = (const float*)d_in[2];
    const float* known_feats  = (const float*)d_in[3];
    const float* W1 = (const float*)d_in[4];
    const float* g1 = (const float*)d_in[5];
    const float* b1 = (const float*)d_in[6];
    const float* W2 = (const float*)d_in[7];
    const float* g2 = (const float*)d_in[8];
    const float* b2 = (const float*)d_in[9];
    float* out = (float*)d_out;

    zero_stats_kernel<<<1, 256>>>();
    knn_kernel<<<dim3(NN/256, BB), 256>>>(unknown, known);
    zgemm_kernel<<<dim3(MM/TN, CO/TM, BB*NR), 256>>>(W1, known_feats);
    transpose_z_kernel<<<dim3(MM/32, CO/32, BB*NR), dim3(32, 8)>>>();
    gemm1_kernel<<<dim3(NN/TN, CO/TM, BB*NR), 256>>>(W1, unknow_feats);
    stats_kernel<<<1, 256>>>(g1, b1, 0);
    gemm2_kernel<<<dim3(NN/TN, CO/TM, BB*NR), 256>>>(W2);
    stats_kernel<<<1, 256>>>(g2, b2, 1);
    final_kernel<<<(int)(((size_t)BB*CO*NR*NN/4 + 255) / 256), 256>>>(out);
}